// round 3
// baseline (speedup 1.0000x reference)
#include <cuda_runtime.h>
#include <cstdint>

#define DD 128
#define NODES_MAX 100000
#define EDGES_MAX 1600000
#define AS_STRIDE 129
#define WS_STRIDE 129
#define GEMM_SMEM (2 * 128 * 129 * (int)sizeof(float))

// Scratch (device globals; no runtime allocation)
__device__ float g_agg[(size_t)NODES_MAX * DD];
__device__ float g_h[(size_t)NODES_MAX * DD];
__device__ int   g_src[EDGES_MAX];
__device__ int   g_dst[EDGES_MAX];
__device__ int   g_is64;

// ---------------------------------------------------------------------------
// Detect edge_index dtype: if the buffer really holds int64 node ids, the
// first few words interpreted as int64 are all in [0, N). If it holds int32
// pairs, an int64 read combines two indices -> out-of-range with prob ~1.
// ---------------------------------------------------------------------------
__global__ void detect_kernel(const void* ei, int n_check, int n_nodes) {
    const long long* p = (const long long*)ei;
    int ok = 1;
    for (int i = 0; i < n_check; i++) {
        long long v = p[i];
        if (v < 0 || v >= n_nodes) { ok = 0; break; }
    }
    g_is64 = ok;
}

// Normalize edge indices to int32 src/dst arrays.
__global__ void convert_kernel(const void* ei, int E) {
    int e = blockIdx.x * blockDim.x + threadIdx.x;
    if (e >= E) return;
    if (g_is64) {
        const long long* p = (const long long*)ei;
        g_src[e] = (int)p[e];
        g_dst[e] = (int)p[(size_t)E + e];
    } else {
        const int* p = (const int*)ei;
        g_src[e] = p[e];
        g_dst[e] = p[E + e];
    }
}

// ---------------------------------------------------------------------------
// Zero-fill (float4 stores)
// ---------------------------------------------------------------------------
__global__ void zero_kernel(float4* __restrict__ p, int n4) {
    int i = blockIdx.x * blockDim.x + threadIdx.x;
    if (i < n4) p[i] = make_float4(0.f, 0.f, 0.f, 0.f);
}

// ---------------------------------------------------------------------------
// Scatter-add: one edge per warp; each lane owns one float4 of the 128-wide
// row. Gather is L2-resident (X is 51 MB, fits in 126 MB L2). Scatter uses
// vector reductions (16B red ops -> 4x fewer L2 atomic transactions).
// Bounds guards turn any index surprise into a rel_err signal, not a crash.
// ---------------------------------------------------------------------------
__global__ void scatter_kernel(const float* __restrict__ X,
                               float* __restrict__ agg, int E, int N) {
    int e = (int)((blockIdx.x * blockDim.x + threadIdx.x) >> 5);
    int lane = threadIdx.x & 31;
    if (e >= E) return;
    int s = g_src[e];   // same addr across warp -> broadcast load
    int d = g_dst[e];
    if ((unsigned)s >= (unsigned)N || (unsigned)d >= (unsigned)N) return;
    float4 v = *(const float4*)(X + (size_t)s * DD + lane * 4);
    float* dp = agg + (size_t)d * DD + lane * 4;
    asm volatile("red.global.add.v4.f32 [%0], {%1, %2, %3, %4};"
                 :: "l"(dp), "f"(v.x), "f"(v.y), "f"(v.z), "f"(v.w)
                 : "memory");
}

// ---------------------------------------------------------------------------
// GEMM + bias + ReLU:  out[i,o] = relu(b[o] + sum_k A[i,k] * W[o,k])
// 256 threads, 128x128 tile, 8x8 register tile per thread. Ws holds W
// transposed with stride 129 (conflict-free strided column reads).
// ---------------------------------------------------------------------------
__global__ __launch_bounds__(256, 1)
void gemm_bias_relu(const float* __restrict__ A, const float* __restrict__ W,
                    const float* __restrict__ bias, float* __restrict__ out,
                    int N) {
    extern __shared__ float sm[];
    float* As = sm;                        // [128][AS_STRIDE]
    float* Ws = sm + 128 * AS_STRIDE;      // Ws[k][o] = W[o][k]
    const int tid = threadIdx.x;
    const int row0 = blockIdx.x * 128;

    for (int i = tid; i < 128 * 32; i += 256) {
        int r = i >> 5;
        int k = (i & 31) * 4;
        int gr = row0 + r;
        float4 v = (gr < N) ? *(const float4*)(A + (size_t)gr * DD + k)
                            : make_float4(0.f, 0.f, 0.f, 0.f);
        float* p = As + r * AS_STRIDE + k;
        p[0] = v.x; p[1] = v.y; p[2] = v.z; p[3] = v.w;
    }
    for (int i = tid; i < 128 * 32; i += 256) {
        int o = i >> 5;
        int kq = (i & 31) * 4;
        float4 v = *(const float4*)(W + o * DD + kq);
        Ws[(kq + 0) * WS_STRIDE + o] = v.x;
        Ws[(kq + 1) * WS_STRIDE + o] = v.y;
        Ws[(kq + 2) * WS_STRIDE + o] = v.z;
        Ws[(kq + 3) * WS_STRIDE + o] = v.w;
    }
    __syncthreads();

    const int tx = tid & 15;
    const int ty = tid >> 4;
    const int r0 = ty * 8;

    float acc[8][8];
#pragma unroll
    for (int i = 0; i < 8; i++)
#pragma unroll
        for (int j = 0; j < 8; j++) acc[i][j] = 0.f;

#pragma unroll 4
    for (int k = 0; k < DD; k++) {
        float a[8], w[8];
#pragma unroll
        for (int i = 0; i < 8; i++) a[i] = As[(r0 + i) * AS_STRIDE + k];
#pragma unroll
        for (int j = 0; j < 8; j++) w[j] = Ws[k * WS_STRIDE + j * 16 + tx];
#pragma unroll
        for (int i = 0; i < 8; i++)
#pragma unroll
            for (int j = 0; j < 8; j++)
                acc[i][j] = fmaf(a[i], w[j], acc[i][j]);
    }

    float bb[8];
#pragma unroll
    for (int j = 0; j < 8; j++) bb[j] = bias[j * 16 + tx];

#pragma unroll
    for (int i = 0; i < 8; i++) {
        int gr = row0 + r0 + i;
        if (gr < N) {
            float* op = out + (size_t)gr * DD;
#pragma unroll
            for (int j = 0; j < 8; j++)
                op[j * 16 + tx] = fmaxf(acc[i][j] + bb[j], 0.f);
        }
    }
}

// ---------------------------------------------------------------------------
extern "C" void kernel_launch(void* const* d_in, const int* in_sizes, int n_in,
                              void* d_out, int out_size) {
    const float* x  = (const float*)d_in[0];
    const void*  ei = d_in[1];
    const float* W1 = (const float*)d_in[2];
    const float* b1 = (const float*)d_in[3];
    const float* W2 = (const float*)d_in[4];
    const float* b2 = (const float*)d_in[5];
    float* out      = (float*)d_out;

    int N = in_sizes[0] / DD;
    int E = in_sizes[1] / 2;

    float *agg, *h;
    cudaGetSymbolAddress((void**)&agg, g_agg);
    cudaGetSymbolAddress((void**)&h, g_h);

    cudaFuncSetAttribute(gemm_bias_relu,
                         cudaFuncAttributeMaxDynamicSharedMemorySize, GEMM_SMEM);

    int n4    = N * (DD / 4);
    int zgrid = (n4 + 255) / 256;
    int cgrid = (E + 255) / 256;
    int sgrid = (E + 7) / 8;       // 8 warps/block, 1 edge/warp
    int ggrid = (N + 127) / 128;

    int n_check = E < 8 ? E : 8;   // int64 view of 2*E words has >= E entries

    // Normalize edge indices (dtype-robust)
    detect_kernel<<<1, 1>>>(ei, n_check, N);
    convert_kernel<<<cgrid, 256>>>(ei, E);

    // Layer 1
    zero_kernel<<<zgrid, 256>>>((float4*)agg, n4);
    scatter_kernel<<<sgrid, 256>>>(x, agg, E, N);
    gemm_bias_relu<<<ggrid, 256, GEMM_SMEM>>>(agg, W1, b1, h, N);

    // Layer 2
    zero_kernel<<<zgrid, 256>>>((float4*)agg, n4);
    scatter_kernel<<<sgrid, 256>>>(h, agg, E, N);
    gemm_bias_relu<<<ggrid, 256, GEMM_SMEM>>>(agg, W2, b2, out, N);
}

// round 4
// speedup vs baseline: 1.2508x; 1.2508x over previous
#include <cuda_runtime.h>
#include <cstdint>

#define DD 128
#define NODES_MAX 100000
#define EDGES_MAX 1600000
#define AS_STRIDE 129   // row-major A tile, scalar broadcast reads
#define WS_STRIDE 132   // k-major W tile, 16B-aligned vector reads
#define GEMM_SMEM ((128 * AS_STRIDE + 128 * WS_STRIDE) * (int)sizeof(float))

// Scratch (device globals; no runtime allocation)
__device__ float g_agg[(size_t)NODES_MAX * DD];
__device__ float g_h[(size_t)NODES_MAX * DD];
__device__ int2  g_edge[EDGES_MAX];            // (src, dst)
__device__ float g_Wt1[DD * DD];               // Wt[k][o] = W[o][k]
__device__ float g_Wt2[DD * DD];
__device__ int   g_is64;

// Packed fp32x2 helpers (sm_100-family packed math: 2 FMA per issue slot)
__device__ __forceinline__ unsigned long long pk2(float lo, float hi) {
    unsigned long long r;
    asm("mov.b64 %0, {%1, %2};" : "=l"(r) : "f"(lo), "f"(hi));
    return r;
}
__device__ __forceinline__ void unpk2(unsigned long long v, float& lo, float& hi) {
    asm("mov.b64 {%0, %1}, %2;" : "=f"(lo), "=f"(hi) : "l"(v));
}
__device__ __forceinline__ unsigned long long fma2(unsigned long long a,
                                                   unsigned long long b,
                                                   unsigned long long c) {
    unsigned long long d;
    asm("fma.rn.f32x2 %0, %1, %2, %3;" : "=l"(d) : "l"(a), "l"(b), "l"(c));
    return d;
}

// ---------------------------------------------------------------------------
// Edge dtype detect (int64 ids in range vs int32 pairs) + normalize to int2.
// ---------------------------------------------------------------------------
__global__ void detect_kernel(const void* ei, int n_check, int n_nodes) {
    const long long* p = (const long long*)ei;
    int ok = 1;
    for (int i = 0; i < n_check; i++) {
        long long v = p[i];
        if (v < 0 || v >= n_nodes) { ok = 0; break; }
    }
    g_is64 = ok;
}

__global__ void convert_kernel(const void* ei, int E) {
    int e = blockIdx.x * blockDim.x + threadIdx.x;
    if (e >= E) return;
    int s, d;
    if (g_is64) {
        const long long* p = (const long long*)ei;
        s = (int)p[e];
        d = (int)p[(size_t)E + e];
    } else {
        const int* p = (const int*)ei;
        s = p[e];
        d = p[E + e];
    }
    g_edge[e] = make_int2(s, d);
}

// 128x128 transpose (tiny, runs once per weight)
__global__ void transpose_kernel(const float* __restrict__ W,
                                 float* __restrict__ Wt) {
    for (int i = blockIdx.x * blockDim.x + threadIdx.x; i < DD * DD;
         i += gridDim.x * blockDim.x) {
        int o = i >> 7, k = i & 127;
        Wt[k * DD + o] = W[i];
    }
}

__global__ void zero_kernel(float4* __restrict__ p, int n4) {
    int i = blockIdx.x * blockDim.x + threadIdx.x;
    if (i < n4) p[i] = make_float4(0.f, 0.f, 0.f, 0.f);
}

// ---------------------------------------------------------------------------
// Scatter-add, 4 edges per warp (MLP=4). Lane owns one float4 of the row.
// Gather is L2-resident; scatter via red.global.add.v4.f32.
// ---------------------------------------------------------------------------
__global__ void scatter_kernel(const float* __restrict__ X,
                               float* __restrict__ agg, int E, int N) {
    int warp = (int)((blockIdx.x * blockDim.x + threadIdx.x) >> 5);
    int lane = threadIdx.x & 31;
    int e0 = warp * 4;
    int2 ed[4];
    float4 v[4];
#pragma unroll
    for (int i = 0; i < 4; i++) {
        int e = e0 + i;
        ed[i] = (e < E) ? g_edge[e] : make_int2(-1, -1);
        if ((unsigned)ed[i].x >= (unsigned)N || (unsigned)ed[i].y >= (unsigned)N)
            ed[i].x = -1;
    }
#pragma unroll
    for (int i = 0; i < 4; i++)
        if (ed[i].x >= 0)
            v[i] = *(const float4*)(X + (size_t)ed[i].x * DD + lane * 4);
#pragma unroll
    for (int i = 0; i < 4; i++)
        if (ed[i].x >= 0) {
            float* dp = agg + (size_t)ed[i].y * DD + lane * 4;
            asm volatile("red.global.add.v4.f32 [%0], {%1, %2, %3, %4};"
                         :: "l"(dp), "f"(v[i].x), "f"(v[i].y), "f"(v[i].z),
                            "f"(v[i].w)
                         : "memory");
        }
}

// ---------------------------------------------------------------------------
// GEMM + bias + ReLU with packed f32x2 FMA.
//   out[i,o] = relu(b[o] + sum_k A[i,k] * Wt[k,o])
// 256 threads, 128x128 tile. Thread (tx,ty): rows ty*8..+7, cols tx*8..+7.
// a-side: 8 scalar LDS (broadcast). w-side: 2x LDS.128 -> 4 packed pairs.
// Inner: 32 fma.rn.f32x2 (= 64 FMA) per k.
// ---------------------------------------------------------------------------
__global__ __launch_bounds__(256, 1)
void gemm_bias_relu(const float* __restrict__ A, const float* __restrict__ Wt,
                    const float* __restrict__ bias, float* __restrict__ out,
                    int N) {
    extern __shared__ float sm[];
    float* As = sm;                       // [128][AS_STRIDE] row-major
    float* Ws = sm + 128 * AS_STRIDE;     // [128][WS_STRIDE], Ws[k][o]=Wt[k][o]
    const int tid = threadIdx.x;
    const int row0 = blockIdx.x * 128;

    // A tile: coalesced float4 global reads, conflict-free scalar smem writes
    for (int i = tid; i < 128 * 32; i += 256) {
        int r = i >> 5;
        int k = (i & 31) * 4;
        int gr = row0 + r;
        float4 v = (gr < N) ? *(const float4*)(A + (size_t)gr * DD + k)
                            : make_float4(0.f, 0.f, 0.f, 0.f);
        float* p = As + r * AS_STRIDE + k;
        p[0] = v.x; p[1] = v.y; p[2] = v.z; p[3] = v.w;
    }
    // W tile: straight coalesced copy of pre-transposed Wt (16B-aligned rows)
    for (int i = tid; i < 128 * 32; i += 256) {
        int k = i >> 5;
        int o = (i & 31) * 4;
        float4 v = *(const float4*)(Wt + k * DD + o);
        *(float4*)(Ws + k * WS_STRIDE + o) = v;
    }
    __syncthreads();

    const int tx = tid & 15;
    const int ty = tid >> 4;
    const int r0 = ty * 8;
    const int c0 = tx * 8;

    unsigned long long acc[8][4];
#pragma unroll
    for (int i = 0; i < 8; i++)
#pragma unroll
        for (int j = 0; j < 4; j++) acc[i][j] = 0ull;

#pragma unroll 2
    for (int k = 0; k < DD; k++) {
        float4 w0 = *(const float4*)(Ws + k * WS_STRIDE + c0);
        float4 w1 = *(const float4*)(Ws + k * WS_STRIDE + c0 + 4);
        unsigned long long wp[4];
        wp[0] = pk2(w0.x, w0.y);
        wp[1] = pk2(w0.z, w0.w);
        wp[2] = pk2(w1.x, w1.y);
        wp[3] = pk2(w1.z, w1.w);
        const float* ak = As + r0 * AS_STRIDE + k;
#pragma unroll
        for (int i = 0; i < 8; i++) {
            float a = ak[i * AS_STRIDE];
            unsigned long long ap = pk2(a, a);
#pragma unroll
            for (int j = 0; j < 4; j++)
                acc[i][j] = fma2(ap, wp[j], acc[i][j]);
        }
    }

    float bb[8];
#pragma unroll
    for (int j = 0; j < 8; j++) bb[j] = bias[c0 + j];

#pragma unroll
    for (int i = 0; i < 8; i++) {
        int gr = row0 + r0 + i;
        if (gr < N) {
            float r[8];
#pragma unroll
            for (int j = 0; j < 4; j++) unpk2(acc[i][j], r[2 * j], r[2 * j + 1]);
            float4 o0, o1;
            o0.x = fmaxf(r[0] + bb[0], 0.f);
            o0.y = fmaxf(r[1] + bb[1], 0.f);
            o0.z = fmaxf(r[2] + bb[2], 0.f);
            o0.w = fmaxf(r[3] + bb[3], 0.f);
            o1.x = fmaxf(r[4] + bb[4], 0.f);
            o1.y = fmaxf(r[5] + bb[5], 0.f);
            o1.z = fmaxf(r[6] + bb[6], 0.f);
            o1.w = fmaxf(r[7] + bb[7], 0.f);
            float* op = out + (size_t)gr * DD + c0;
            *(float4*)op = o0;
            *(float4*)(op + 4) = o1;
        }
    }
}

// ---------------------------------------------------------------------------
extern "C" void kernel_launch(void* const* d_in, const int* in_sizes, int n_in,
                              void* d_out, int out_size) {
    const float* x  = (const float*)d_in[0];
    const void*  ei = d_in[1];
    const float* W1 = (const float*)d_in[2];
    const float* b1 = (const float*)d_in[3];
    const float* W2 = (const float*)d_in[4];
    const float* b2 = (const float*)d_in[5];
    float* out      = (float*)d_out;

    int N = in_sizes[0] / DD;
    int E = in_sizes[1] / 2;

    float *agg, *h, *wt1, *wt2;
    cudaGetSymbolAddress((void**)&agg, g_agg);
    cudaGetSymbolAddress((void**)&h, g_h);
    cudaGetSymbolAddress((void**)&wt1, g_Wt1);
    cudaGetSymbolAddress((void**)&wt2, g_Wt2);

    cudaFuncSetAttribute(gemm_bias_relu,
                         cudaFuncAttributeMaxDynamicSharedMemorySize, GEMM_SMEM);

    int n4    = N * (DD / 4);
    int zgrid = (n4 + 255) / 256;
    int cgrid = (E + 255) / 256;
    int sgrid = (E + 31) / 32;     // 8 warps/block, 4 edges/warp
    int ggrid = (N + 127) / 128;
    int n_check = E < 8 ? E : 8;

    detect_kernel<<<1, 1>>>(ei, n_check, N);
    convert_kernel<<<cgrid, 256>>>(ei, E);
    transpose_kernel<<<64, 256>>>(W1, wt1);
    transpose_kernel<<<64, 256>>>(W2, wt2);

    // Layer 1
    zero_kernel<<<zgrid, 256>>>((float4*)agg, n4);
    scatter_kernel<<<sgrid, 256>>>(x, agg, E, N);
    gemm_bias_relu<<<ggrid, 256, GEMM_SMEM>>>(agg, wt1, b1, h, N);

    // Layer 2
    zero_kernel<<<zgrid, 256>>>((float4*)agg, n4);
    scatter_kernel<<<sgrid, 256>>>(h, agg, E, N);
    gemm_bias_relu<<<ggrid, 256, GEMM_SMEM>>>(agg, wt2, b2, out, N);
}

// round 6
// speedup vs baseline: 1.6120x; 1.2888x over previous
#include <cuda_runtime.h>
#include <cstdint>

#define DD 128
#define NODES_MAX 100000
#define EDGES_MAX 1600000
#define SCAN_N (NODES_MAX + 1)
#define SCAN_CHUNK 1024
#define AS_STRIDE 129   // A tile: scalar broadcast reads, pad to kill conflicts
#define WS_STRIDE 128   // W tile: uniform-k vector reads
#define GEMM_SMEM ((128 * AS_STRIDE + 128 * WS_STRIDE) * (int)sizeof(float))

// Scratch (device globals; no runtime allocation)
__device__ float g_agg[(size_t)NODES_MAX * DD];
__device__ float g_h[(size_t)NODES_MAX * DD];
__device__ int2  g_edge[EDGES_MAX];     // (src, dst)
__device__ int   g_esrc[EDGES_MAX];     // src ids, sorted by dst (CSR adj)
__device__ int   g_rowptr[SCAN_N];      // CSR row pointers
__device__ int   g_pos[NODES_MAX];      // placement cursors
__device__ int   g_bsum[128];           // scan block sums
__device__ float g_Wt1[DD * DD];        // Wt[k][o] = W[o][k]
__device__ float g_Wt2[DD * DD];
__device__ int   g_is64;

// Packed fp32x2 helpers (2 FMA per issue slot on sm_100)
__device__ __forceinline__ unsigned long long pk2(float lo, float hi) {
    unsigned long long r;
    asm("mov.b64 %0, {%1, %2};" : "=l"(r) : "f"(lo), "f"(hi));
    return r;
}
__device__ __forceinline__ void unpk2(unsigned long long v, float& lo, float& hi) {
    asm("mov.b64 {%0, %1}, %2;" : "=f"(lo), "=f"(hi) : "l"(v));
}
__device__ __forceinline__ unsigned long long fma2(unsigned long long a,
                                                   unsigned long long b,
                                                   unsigned long long c) {
    unsigned long long d;
    asm("fma.rn.f32x2 %0, %1, %2, %3;" : "=l"(d) : "l"(a), "l"(b), "l"(c));
    return d;
}

// ---------------------------------------------------------------------------
// Edge dtype detect (int64 ids in range vs int32 pairs)
// ---------------------------------------------------------------------------
__global__ void detect_kernel(const void* ei, int n_check, int n_nodes) {
    const long long* p = (const long long*)ei;
    int ok = 1;
    for (int i = 0; i < n_check; i++) {
        long long v = p[i];
        if (v < 0 || v >= n_nodes) { ok = 0; break; }
    }
    g_is64 = ok;
}

__global__ void zero_cnt_kernel(int n) {
    int i = blockIdx.x * blockDim.x + threadIdx.x;
    if (i < n) g_rowptr[i] = 0;
}

// Normalize edges to int2 AND histogram dst into g_rowptr[d+1].
__global__ void convert_hist_kernel(const void* ei, int E, int N) {
    int e = blockIdx.x * blockDim.x + threadIdx.x;
    if (e >= E) return;
    int s, d;
    if (g_is64) {
        const long long* p = (const long long*)ei;
        s = (int)p[e];
        d = (int)p[(size_t)E + e];
    } else {
        const int* p = (const int*)ei;
        s = p[e];
        d = p[E + e];
    }
    if ((unsigned)s >= (unsigned)N) s = 0;   // clamp (ref guarantees in-range)
    if ((unsigned)d >= (unsigned)N) d = 0;
    g_edge[e] = make_int2(s, d);
    atomicAdd(&g_rowptr[d + 1], 1);
}

// ---- 3-pass exclusive scan of counts -> row_ptr -------------------------
__global__ void scan1_kernel(int n) {
    __shared__ int sh[SCAN_CHUNK];
    int i = blockIdx.x * SCAN_CHUNK + threadIdx.x;
    sh[threadIdx.x] = (i < n) ? g_rowptr[i] : 0;
    __syncthreads();
    for (int off = 1; off < SCAN_CHUNK; off <<= 1) {
        int t = (threadIdx.x >= off) ? sh[threadIdx.x - off] : 0;
        __syncthreads();
        sh[threadIdx.x] += t;
        __syncthreads();
    }
    if (i < n) g_rowptr[i] = sh[threadIdx.x];
    if (threadIdx.x == SCAN_CHUNK - 1) g_bsum[blockIdx.x] = sh[threadIdx.x];
}

__global__ void scan2_kernel(int nb) {
    int lane = threadIdx.x;   // 32 threads
    int carry = 0;
    for (int base = 0; base < nb; base += 32) {
        int i = base + lane;
        int orig = (i < nb) ? g_bsum[i] : 0;
        int v = orig;
#pragma unroll
        for (int off = 1; off < 32; off <<= 1) {
            int t = __shfl_up_sync(0xffffffffu, v, off);
            if (lane >= off) v += t;
        }
        if (i < nb) g_bsum[i] = carry + v - orig;   // exclusive block offset
        carry += __shfl_sync(0xffffffffu, v, 31);
    }
}

__global__ void scan3_kernel(int n, int N) {
    int i = blockIdx.x * blockDim.x + threadIdx.x;
    if (i >= n) return;
    int v = g_rowptr[i] + g_bsum[i >> 10];
    g_rowptr[i] = v;
    if (i < N) g_pos[i] = v;    // placement cursor = row start
}

// Place src ids into dst-sorted order.
__global__ void place_kernel(int E) {
    int e = blockIdx.x * blockDim.x + threadIdx.x;
    if (e >= E) return;
    int2 ed = g_edge[e];
    int p = atomicAdd(&g_pos[ed.y], 1);
    g_esrc[p] = ed.x;
}

// Transpose both weight matrices in one kernel.
__global__ void transpose_kernel(const float* __restrict__ W1,
                                 const float* __restrict__ W2) {
    for (int i = blockIdx.x * blockDim.x + threadIdx.x; i < 2 * DD * DD;
         i += gridDim.x * blockDim.x) {
        int which = i >= DD * DD;
        int j = i - which * DD * DD;
        int o = j >> 7, k = j & 127;
        (which ? g_Wt2 : g_Wt1)[k * DD + o] = (which ? W2 : W1)[j];
    }
}

// ---------------------------------------------------------------------------
// CSR aggregation: warp per node, lane owns one float4 of the 128-wide row.
// 4 accumulators -> 4 outstanding gathers. Plain store, no atomics, no zero.
// ---------------------------------------------------------------------------
__global__ void csr_agg_kernel(const float* __restrict__ X,
                               float* __restrict__ agg, int N) {
    int node = (int)((blockIdx.x * blockDim.x + threadIdx.x) >> 5);
    int lane = threadIdx.x & 31;
    if (node >= N) return;
    int j   = g_rowptr[node];
    int end = g_rowptr[node + 1];
    float4 a0 = make_float4(0.f, 0.f, 0.f, 0.f), a1 = a0, a2 = a0, a3 = a0;
    for (; j + 3 < end; j += 4) {
        int s0 = g_esrc[j], s1 = g_esrc[j + 1];
        int s2 = g_esrc[j + 2], s3 = g_esrc[j + 3];
        float4 v0 = *(const float4*)(X + (size_t)s0 * DD + lane * 4);
        float4 v1 = *(const float4*)(X + (size_t)s1 * DD + lane * 4);
        float4 v2 = *(const float4*)(X + (size_t)s2 * DD + lane * 4);
        float4 v3 = *(const float4*)(X + (size_t)s3 * DD + lane * 4);
        a0.x += v0.x; a0.y += v0.y; a0.z += v0.z; a0.w += v0.w;
        a1.x += v1.x; a1.y += v1.y; a1.z += v1.z; a1.w += v1.w;
        a2.x += v2.x; a2.y += v2.y; a2.z += v2.z; a2.w += v2.w;
        a3.x += v3.x; a3.y += v3.y; a3.z += v3.z; a3.w += v3.w;
    }
    for (; j < end; j++) {
        int s = g_esrc[j];
        float4 v = *(const float4*)(X + (size_t)s * DD + lane * 4);
        a0.x += v.x; a0.y += v.y; a0.z += v.z; a0.w += v.w;
    }
    a0.x += a1.x + a2.x + a3.x;
    a0.y += a1.y + a2.y + a3.y;
    a0.z += a1.z + a2.z + a3.z;
    a0.w += a1.w + a2.w + a3.w;
    *(float4*)(agg + (size_t)node * DD + lane * 4) = a0;
}

// ---------------------------------------------------------------------------
// GEMM + bias + ReLU, packed f32x2 FMA.
// Thread (tx,ty): rows ty*8..+7, cols {4tx..4tx+3} u {64+4tx..64+4tx+3}.
// ---------------------------------------------------------------------------
__global__ __launch_bounds__(256, 1)
void gemm_bias_relu(const float* __restrict__ A, const float* __restrict__ Wt,
                    const float* __restrict__ bias, float* __restrict__ out,
                    int N) {
    extern __shared__ float sm[];
    float* As = sm;                       // [128][AS_STRIDE]
    float* Ws = sm + 128 * AS_STRIDE;     // [128][WS_STRIDE] = Wt rows
    const int tid = threadIdx.x;
    const int row0 = blockIdx.x * 128;

    for (int i = tid; i < 128 * 32; i += 256) {
        int r = i >> 5;
        int k = (i & 31) * 4;
        int gr = row0 + r;
        float4 v = (gr < N) ? *(const float4*)(A + (size_t)gr * DD + k)
                            : make_float4(0.f, 0.f, 0.f, 0.f);
        float* p = As + r * AS_STRIDE + k;
        p[0] = v.x; p[1] = v.y; p[2] = v.z; p[3] = v.w;
    }
    for (int i = tid; i < 128 * 32; i += 256) {
        int k = i >> 5;
        int o = (i & 31) * 4;
        *(float4*)(Ws + k * WS_STRIDE + o) = *(const float4*)(Wt + k * DD + o);
    }
    __syncthreads();

    const int tx = tid & 15;
    const int ty = tid >> 4;
    const int r0 = ty * 8;
    const int c0 = tx * 4;        // cols c0..c0+3 and c0+64..c0+67

    unsigned long long acc[8][4];
#pragma unroll
    for (int i = 0; i < 8; i++)
#pragma unroll
        for (int j = 0; j < 4; j++) acc[i][j] = 0ull;

#pragma unroll 2
    for (int k = 0; k < DD; k++) {
        float4 w0 = *(const float4*)(Ws + k * WS_STRIDE + c0);
        float4 w1 = *(const float4*)(Ws + k * WS_STRIDE + c0 + 64);
        unsigned long long wp[4];
        wp[0] = pk2(w0.x, w0.y);
        wp[1] = pk2(w0.z, w0.w);
        wp[2] = pk2(w1.x, w1.y);
        wp[3] = pk2(w1.z, w1.w);
        const float* ak = As + r0 * AS_STRIDE + k;
#pragma unroll
        for (int i = 0; i < 8; i++) {
            float a = ak[i * AS_STRIDE];
            unsigned long long ap = pk2(a, a);
#pragma unroll
            for (int j = 0; j < 4; j++)
                acc[i][j] = fma2(ap, wp[j], acc[i][j]);
        }
    }

    float4 bb0 = *(const float4*)(bias + c0);
    float4 bb1 = *(const float4*)(bias + c0 + 64);

#pragma unroll
    for (int i = 0; i < 8; i++) {
        int gr = row0 + r0 + i;
        if (gr < N) {
            float r[8];
#pragma unroll
            for (int j = 0; j < 4; j++) unpk2(acc[i][j], r[2 * j], r[2 * j + 1]);
            float4 o0, o1;
            o0.x = fmaxf(r[0] + bb0.x, 0.f);
            o0.y = fmaxf(r[1] + bb0.y, 0.f);
            o0.z = fmaxf(r[2] + bb0.z, 0.f);
            o0.w = fmaxf(r[3] + bb0.w, 0.f);
            o1.x = fmaxf(r[4] + bb1.x, 0.f);
            o1.y = fmaxf(r[5] + bb1.y, 0.f);
            o1.z = fmaxf(r[6] + bb1.z, 0.f);
            o1.w = fmaxf(r[7] + bb1.w, 0.f);
            float* op = out + (size_t)gr * DD;
            *(float4*)(op + c0) = o0;
            *(float4*)(op + c0 + 64) = o1;
        }
    }
}

// ---------------------------------------------------------------------------
extern "C" void kernel_launch(void* const* d_in, const int* in_sizes, int n_in,
                              void* d_out, int out_size) {
    const float* x  = (const float*)d_in[0];
    const void*  ei = d_in[1];
    const float* W1 = (const float*)d_in[2];
    const float* b1 = (const float*)d_in[3];
    const float* W2 = (const float*)d_in[4];
    const float* b2 = (const float*)d_in[5];
    float* out      = (float*)d_out;

    int N = in_sizes[0] / DD;
    int E = in_sizes[1] / 2;

    float *agg, *h, *wt1, *wt2;
    cudaGetSymbolAddress((void**)&agg, g_agg);
    cudaGetSymbolAddress((void**)&h, g_h);
    cudaGetSymbolAddress((void**)&wt1, g_Wt1);
    cudaGetSymbolAddress((void**)&wt2, g_Wt2);

    cudaFuncSetAttribute(gemm_bias_relu,
                         cudaFuncAttributeMaxDynamicSharedMemorySize, GEMM_SMEM);

    int n       = N + 1;
    int nb      = (n + SCAN_CHUNK - 1) / SCAN_CHUNK;
    int cgrid   = (E + 255) / 256;
    int agrid   = (N * 32 + 255) / 256;   // warp per node
    int ggrid   = (N + 127) / 128;
    int n_check = E < 8 ? E : 8;

    // Build CSR (once; reused by both layers)
    detect_kernel<<<1, 1>>>(ei, n_check, N);
    zero_cnt_kernel<<<(n + 255) / 256, 256>>>(n);
    convert_hist_kernel<<<cgrid, 256>>>(ei, E, N);
    scan1_kernel<<<nb, SCAN_CHUNK>>>(n);
    scan2_kernel<<<1, 32>>>(nb);
    scan3_kernel<<<(n + 255) / 256, 256>>>(n, N);
    place_kernel<<<cgrid, 256>>>(E);
    transpose_kernel<<<128, 256>>>(W1, W2);

    // Layer 1
    csr_agg_kernel<<<agrid, 256>>>(x, agg, N);
    gemm_bias_relu<<<ggrid, 256, GEMM_SMEM>>>(agg, wt1, b1, h, N);

    // Layer 2
    csr_agg_kernel<<<agrid, 256>>>(h, agg, N);
    gemm_bias_relu<<<ggrid, 256, GEMM_SMEM>>>(agg, wt2, b2, out, N);
}

// round 7
// speedup vs baseline: 1.6999x; 1.0545x over previous
#include <cuda_runtime.h>
#include <cstdint>

#define DD 128
#define NODES_MAX 100000
#define EDGES_MAX 1600000
#define SCAN_N (NODES_MAX + 1)
#define SCAN_CHUNK 1024
#define AS_STRIDE 132   // even & 16B-aligned rows: float2/float4 access ok
#define GEMM_SMEM ((128 * AS_STRIDE) * (int)sizeof(float) + 64 * 128 * (int)sizeof(float2))

// Scratch (device globals; no runtime allocation)
__device__ float  g_agg[(size_t)NODES_MAX * DD];
__device__ float  g_h[(size_t)NODES_MAX * DD];
__device__ int2   g_edge[EDGES_MAX];     // (src, dst)
__device__ int    g_esrc[EDGES_MAX];     // src ids, sorted by dst (CSR adj)
__device__ int    g_rowptr[SCAN_N];      // CSR row pointers
__device__ int    g_pos[NODES_MAX];      // placement cursors
__device__ int    g_bsum[128];           // scan block sums
__device__ float2 g_Wp1[64 * DD];        // Wp[kk][o] = (W[o][2kk], W[o][2kk+1])
__device__ float2 g_Wp2[64 * DD];
__device__ int    g_is64;

// fma.rn.f32x2: two independent fp32 FMAs per issue slot
__device__ __forceinline__ unsigned long long fma2(unsigned long long a,
                                                   unsigned long long b,
                                                   unsigned long long c) {
    unsigned long long d;
    asm("fma.rn.f32x2 %0, %1, %2, %3;" : "=l"(d) : "l"(a), "l"(b), "l"(c));
    return d;
}
__device__ __forceinline__ void unpk2(unsigned long long v, float& lo, float& hi) {
    asm("mov.b64 {%0, %1}, %2;" : "=f"(lo), "=f"(hi) : "l"(v));
}

// ---------------------------------------------------------------------------
// Edge dtype detect (int64 ids in range vs int32 pairs)
// ---------------------------------------------------------------------------
__global__ void detect_kernel(const void* ei, int n_check, int n_nodes) {
    const long long* p = (const long long*)ei;
    int ok = 1;
    for (int i = 0; i < n_check; i++) {
        long long v = p[i];
        if (v < 0 || v >= n_nodes) { ok = 0; break; }
    }
    g_is64 = ok;
}

__global__ void zero_cnt_kernel(int n) {
    int i = blockIdx.x * blockDim.x + threadIdx.x;
    if (i < n) g_rowptr[i] = 0;
}

// Normalize edges to int2 AND histogram dst into g_rowptr[d+1].
__global__ void convert_hist_kernel(const void* ei, int E, int N) {
    int e = blockIdx.x * blockDim.x + threadIdx.x;
    if (e >= E) return;
    int s, d;
    if (g_is64) {
        const long long* p = (const long long*)ei;
        s = (int)p[e];
        d = (int)p[(size_t)E + e];
    } else {
        const int* p = (const int*)ei;
        s = p[e];
        d = p[E + e];
    }
    if ((unsigned)s >= (unsigned)N) s = 0;   // clamp (ref guarantees in-range)
    if ((unsigned)d >= (unsigned)N) d = 0;
    g_edge[e] = make_int2(s, d);
    atomicAdd(&g_rowptr[d + 1], 1);
}

// ---- 3-pass exclusive scan of counts -> row_ptr -------------------------
__global__ void scan1_kernel(int n) {
    __shared__ int sh[SCAN_CHUNK];
    int i = blockIdx.x * SCAN_CHUNK + threadIdx.x;
    sh[threadIdx.x] = (i < n) ? g_rowptr[i] : 0;
    __syncthreads();
    for (int off = 1; off < SCAN_CHUNK; off <<= 1) {
        int t = (threadIdx.x >= off) ? sh[threadIdx.x - off] : 0;
        __syncthreads();
        sh[threadIdx.x] += t;
        __syncthreads();
    }
    if (i < n) g_rowptr[i] = sh[threadIdx.x];
    if (threadIdx.x == SCAN_CHUNK - 1) g_bsum[blockIdx.x] = sh[threadIdx.x];
}

__global__ void scan2_kernel(int nb) {
    int lane = threadIdx.x;   // 32 threads
    int carry = 0;
    for (int base = 0; base < nb; base += 32) {
        int i = base + lane;
        int orig = (i < nb) ? g_bsum[i] : 0;
        int v = orig;
#pragma unroll
        for (int off = 1; off < 32; off <<= 1) {
            int t = __shfl_up_sync(0xffffffffu, v, off);
            if (lane >= off) v += t;
        }
        if (i < nb) g_bsum[i] = carry + v - orig;   // exclusive block offset
        carry += __shfl_sync(0xffffffffu, v, 31);
    }
}

__global__ void scan3_kernel(int n, int N) {
    int i = blockIdx.x * blockDim.x + threadIdx.x;
    if (i >= n) return;
    int v = g_rowptr[i] + g_bsum[i >> 10];
    g_rowptr[i] = v;
    if (i < N) g_pos[i] = v;    // placement cursor = row start
}

// Place src ids into dst-sorted order.
__global__ void place_kernel(int E) {
    int e = blockIdx.x * blockDim.x + threadIdx.x;
    if (e >= E) return;
    int2 ed = g_edge[e];
    int p = atomicAdd(&g_pos[ed.y], 1);
    g_esrc[p] = ed.x;
}

// Build k-paired transposed weights: Wp[kk][o] = (W[o][2kk], W[o][2kk+1]).
__global__ void wpack_kernel(const float* __restrict__ W1,
                             const float* __restrict__ W2) {
    for (int i = blockIdx.x * blockDim.x + threadIdx.x; i < 2 * 64 * DD;
         i += gridDim.x * blockDim.x) {
        int which = i >= 64 * DD;
        int j = i - which * 64 * DD;
        int kk = j >> 7, o = j & 127;
        const float* W = which ? W2 : W1;
        float2 v = make_float2(W[o * DD + 2 * kk], W[o * DD + 2 * kk + 1]);
        (which ? g_Wp2 : g_Wp1)[kk * DD + o] = v;
    }
}

// ---------------------------------------------------------------------------
// CSR aggregation: warp per node, lane owns one float4 of the 128-wide row.
// 4 accumulators -> 4 outstanding gathers. Plain store, no atomics, no zero.
// (Measured ~87% of L2 read ceiling -> leave unchanged.)
// ---------------------------------------------------------------------------
__global__ void csr_agg_kernel(const float* __restrict__ X,
                               float* __restrict__ agg, int N) {
    int node = (int)((blockIdx.x * blockDim.x + threadIdx.x) >> 5);
    int lane = threadIdx.x & 31;
    if (node >= N) return;
    int j   = g_rowptr[node];
    int end = g_rowptr[node + 1];
    float4 a0 = make_float4(0.f, 0.f, 0.f, 0.f), a1 = a0, a2 = a0, a3 = a0;
    for (; j + 3 < end; j += 4) {
        int s0 = g_esrc[j], s1 = g_esrc[j + 1];
        int s2 = g_esrc[j + 2], s3 = g_esrc[j + 3];
        float4 v0 = *(const float4*)(X + (size_t)s0 * DD + lane * 4);
        float4 v1 = *(const float4*)(X + (size_t)s1 * DD + lane * 4);
        float4 v2 = *(const float4*)(X + (size_t)s2 * DD + lane * 4);
        float4 v3 = *(const float4*)(X + (size_t)s3 * DD + lane * 4);
        a0.x += v0.x; a0.y += v0.y; a0.z += v0.z; a0.w += v0.w;
        a1.x += v1.x; a1.y += v1.y; a1.z += v1.z; a1.w += v1.w;
        a2.x += v2.x; a2.y += v2.y; a2.z += v2.z; a2.w += v2.w;
        a3.x += v3.x; a3.y += v3.y; a3.z += v3.z; a3.w += v3.w;
    }
    for (; j < end; j++) {
        int s = g_esrc[j];
        float4 v = *(const float4*)(X + (size_t)s * DD + lane * 4);
        a0.x += v.x; a0.y += v.y; a0.z += v.z; a0.w += v.w;
    }
    a0.x += a1.x + a2.x + a3.x;
    a0.y += a1.y + a2.y + a3.y;
    a0.z += a1.z + a2.z + a3.z;
    a0.w += a1.w + a2.w + a3.w;
    *(float4*)(agg + (size_t)node * DD + lane * 4) = a0;
}

// ---------------------------------------------------------------------------
// GEMM + bias + ReLU, k-paired f32x2 FMA, 512 threads.
// Thread (tx,ty): tx=tid&31, ty=tid>>5. Rows 8ty..8ty+7, cols tx+32j (j<4).
// Per kk (k-pair): 8 broadcast LDS.64 (a), 4 LDS.64 (w), 32 fma2 — no movs.
// acc lanes hold even-k / odd-k partial sums; horizontal add in epilogue.
// ---------------------------------------------------------------------------
__global__ __launch_bounds__(512, 1)
void gemm_bias_relu(const float* __restrict__ A, const float2* __restrict__ Wp,
                    const float* __restrict__ bias, float* __restrict__ out,
                    int N) {
    extern __shared__ float sm[];
    float* As = sm;                                  // [128][AS_STRIDE]
    unsigned long long* Ws = (unsigned long long*)(sm + 128 * AS_STRIDE); // [64][128] k-pairs
    const int tid = threadIdx.x;
    const int row0 = blockIdx.x * 128;

    // A tile: coalesced float4 reads, aligned float4 smem writes
    for (int i = tid; i < 128 * 32; i += 512) {
        int r = i >> 5;
        int k = (i & 31) * 4;
        int gr = row0 + r;
        float4 v = (gr < N) ? *(const float4*)(A + (size_t)gr * DD + k)
                            : make_float4(0.f, 0.f, 0.f, 0.f);
        *(float4*)(As + r * AS_STRIDE + k) = v;
    }
    // W k-pair tile: straight copy (64*128 float2 = 8192 u64)
    for (int i = tid; i < 64 * 128; i += 512)
        Ws[i] = ((const unsigned long long*)Wp)[i];
    __syncthreads();

    const int tx = tid & 31;
    const int ty = tid >> 5;
    const int r0 = ty * 8;

    unsigned long long acc[8][4];
#pragma unroll
    for (int i = 0; i < 8; i++)
#pragma unroll
        for (int j = 0; j < 4; j++) acc[i][j] = 0ull;

#pragma unroll 2
    for (int kk = 0; kk < 64; kk++) {
        unsigned long long wv[4];
#pragma unroll
        for (int j = 0; j < 4; j++)
            wv[j] = Ws[kk * 128 + tx + 32 * j];
        unsigned long long av[8];
#pragma unroll
        for (int i = 0; i < 8; i++)
            av[i] = *(const unsigned long long*)(As + (r0 + i) * AS_STRIDE + 2 * kk);
#pragma unroll
        for (int i = 0; i < 8; i++)
#pragma unroll
            for (int j = 0; j < 4; j++)
                acc[i][j] = fma2(av[i], wv[j], acc[i][j]);
    }

    float bb[4];
#pragma unroll
    for (int j = 0; j < 4; j++) bb[j] = bias[tx + 32 * j];

#pragma unroll
    for (int i = 0; i < 8; i++) {
        int gr = row0 + r0 + i;
        if (gr < N) {
            float* op = out + (size_t)gr * DD;
#pragma unroll
            for (int j = 0; j < 4; j++) {
                float lo, hi;
                unpk2(acc[i][j], lo, hi);
                op[tx + 32 * j] = fmaxf(lo + hi + bb[j], 0.f);
            }
        }
    }
}

// ---------------------------------------------------------------------------
extern "C" void kernel_launch(void* const* d_in, const int* in_sizes, int n_in,
                              void* d_out, int out_size) {
    const float* x  = (const float*)d_in[0];
    const void*  ei = d_in[1];
    const float* W1 = (const float*)d_in[2];
    const float* b1 = (const float*)d_in[3];
    const float* W2 = (const float*)d_in[4];
    const float* b2 = (const float*)d_in[5];
    float* out      = (float*)d_out;

    int N = in_sizes[0] / DD;
    int E = in_sizes[1] / 2;

    float *agg, *h;
    float2 *wp1, *wp2;
    cudaGetSymbolAddress((void**)&agg, g_agg);
    cudaGetSymbolAddress((void**)&h, g_h);
    cudaGetSymbolAddress((void**)&wp1, g_Wp1);
    cudaGetSymbolAddress((void**)&wp2, g_Wp2);

    cudaFuncSetAttribute(gemm_bias_relu,
                         cudaFuncAttributeMaxDynamicSharedMemorySize, GEMM_SMEM);

    int n       = N + 1;
    int nb      = (n + SCAN_CHUNK - 1) / SCAN_CHUNK;
    int cgrid   = (E + 255) / 256;
    int agrid   = (N * 32 + 255) / 256;   // warp per node
    int ggrid   = (N + 127) / 128;
    int n_check = E < 8 ? E : 8;

    // Build CSR (once; reused by both layers)
    detect_kernel<<<1, 1>>>(ei, n_check, N);
    zero_cnt_kernel<<<(n + 255) / 256, 256>>>(n);
    convert_hist_kernel<<<cgrid, 256>>>(ei, E, N);
    scan1_kernel<<<nb, SCAN_CHUNK>>>(n);
    scan2_kernel<<<1, 32>>>(nb);
    scan3_kernel<<<(n + 255) / 256, 256>>>(n, N);
    place_kernel<<<cgrid, 256>>>(E);
    wpack_kernel<<<64, 256>>>(W1, W2);

    // Layer 1
    csr_agg_kernel<<<agrid, 256>>>(x, agg, N);
    gemm_bias_relu<<<ggrid, 512, GEMM_SMEM>>>(agg, wp1, b1, h, N);

    // Layer 2
    csr_agg_kernel<<<agrid, 256>>>(h, agg, N);
    gemm_bias_relu<<<ggrid, 512, GEMM_SMEM>>>(agg, wp2, b2, out, N);
}

// round 9
// speedup vs baseline: 2.0141x; 1.1848x over previous
#include <cuda_runtime.h>
#include <cuda_bf16.h>
#include <cstdint>

#define DD 128
#define NODES_MAX 100000
#define EDGES_MAX 1600000
#define SCAN_N (NODES_MAX + 1)
#define SCAN_CHUNK 1024

// ---------------- device scratch (no runtime allocation) -------------------
__device__ float  g_agg[(size_t)NODES_MAX * DD];
__device__ float  g_h[(size_t)NODES_MAX * DD];
__device__ int2   g_edge[EDGES_MAX];
__device__ int    g_esrc[EDGES_MAX];
__device__ int    g_rowptr[SCAN_N];
__device__ int    g_pos[NODES_MAX];
__device__ int    g_bsum[128];
__device__ int    g_is64;
// bf16 hi/lo weights, row-major [o][k] (the exact B layout row.col mma wants)
__device__ __align__(16) __nv_bfloat16 g_Whi[2][DD * DD];
__device__ __align__(16) __nv_bfloat16 g_Wlo[2][DD * DD];

// ---------------- warp-mma helpers (sm_80+ PTX, valid on compute_100) ------
__device__ __forceinline__ uint32_t smem_u32(const void* p) {
    uint32_t a;
    asm("{ .reg .u64 t; cvta.to.shared.u64 t, %1; cvt.u32.u64 %0, t; }"
        : "=r"(a) : "l"(p));
    return a;
}
__device__ __forceinline__ void ldm_x4(uint32_t& r0, uint32_t& r1,
                                       uint32_t& r2, uint32_t& r3,
                                       uint32_t addr) {
    asm volatile("ldmatrix.sync.aligned.m8n8.x4.shared.b16 {%0,%1,%2,%3}, [%4];"
                 : "=r"(r0), "=r"(r1), "=r"(r2), "=r"(r3) : "r"(addr));
}
__device__ __forceinline__ void mma_bf16(float* c, const uint32_t* a,
                                         uint32_t b0, uint32_t b1) {
    asm volatile(
        "mma.sync.aligned.m16n8k16.row.col.f32.bf16.bf16.f32 "
        "{%0,%1,%2,%3}, {%4,%5,%6,%7}, {%8,%9}, {%0,%1,%2,%3};"
        : "+f"(c[0]), "+f"(c[1]), "+f"(c[2]), "+f"(c[3])
        : "r"(a[0]), "r"(a[1]), "r"(a[2]), "r"(a[3]), "r"(b0), "r"(b1));
}

// ---------------- CSR build pipeline (unchanged) ---------------------------
__global__ void detect_kernel(const void* ei, int n_check, int n_nodes) {
    const long long* p = (const long long*)ei;
    int ok = 1;
    for (int i = 0; i < n_check; i++) {
        long long v = p[i];
        if (v < 0 || v >= n_nodes) { ok = 0; break; }
    }
    g_is64 = ok;
}

__global__ void zero_cnt_kernel(int n) {
    int i = blockIdx.x * blockDim.x + threadIdx.x;
    if (i < n) g_rowptr[i] = 0;
}

__global__ void convert_hist_kernel(const void* ei, int E, int N) {
    int e = blockIdx.x * blockDim.x + threadIdx.x;
    if (e >= E) return;
    int s, d;
    if (g_is64) {
        const long long* p = (const long long*)ei;
        s = (int)p[e];
        d = (int)p[(size_t)E + e];
    } else {
        const int* p = (const int*)ei;
        s = p[e];
        d = p[E + e];
    }
    if ((unsigned)s >= (unsigned)N) s = 0;
    if ((unsigned)d >= (unsigned)N) d = 0;
    g_edge[e] = make_int2(s, d);
    atomicAdd(&g_rowptr[d + 1], 1);
}

__global__ void scan1_kernel(int n) {
    __shared__ int sh[SCAN_CHUNK];
    int i = blockIdx.x * SCAN_CHUNK + threadIdx.x;
    sh[threadIdx.x] = (i < n) ? g_rowptr[i] : 0;
    __syncthreads();
    for (int off = 1; off < SCAN_CHUNK; off <<= 1) {
        int t = (threadIdx.x >= off) ? sh[threadIdx.x - off] : 0;
        __syncthreads();
        sh[threadIdx.x] += t;
        __syncthreads();
    }
    if (i < n) g_rowptr[i] = sh[threadIdx.x];
    if (threadIdx.x == SCAN_CHUNK - 1) g_bsum[blockIdx.x] = sh[threadIdx.x];
}

__global__ void scan2_kernel(int nb) {
    int lane = threadIdx.x;
    int carry = 0;
    for (int base = 0; base < nb; base += 32) {
        int i = base + lane;
        int orig = (i < nb) ? g_bsum[i] : 0;
        int v = orig;
#pragma unroll
        for (int off = 1; off < 32; off <<= 1) {
            int t = __shfl_up_sync(0xffffffffu, v, off);
            if (lane >= off) v += t;
        }
        if (i < nb) g_bsum[i] = carry + v - orig;
        carry += __shfl_sync(0xffffffffu, v, 31);
    }
}

__global__ void scan3_kernel(int n, int N) {
    int i = blockIdx.x * blockDim.x + threadIdx.x;
    if (i >= n) return;
    int v = g_rowptr[i] + g_bsum[i >> 10];
    g_rowptr[i] = v;
    if (i < N) g_pos[i] = v;
}

__global__ void place_kernel(int E) {
    int e = blockIdx.x * blockDim.x + threadIdx.x;
    if (e >= E) return;
    int2 ed = g_edge[e];
    int p = atomicAdd(&g_pos[ed.y], 1);
    g_esrc[p] = ed.x;
}

// Split weights into bf16 hi/lo (row-major [o][k], no swizzle needed).
__global__ void bpack_kernel(const float* __restrict__ W1,
                             const float* __restrict__ W2) {
    for (int i = blockIdx.x * blockDim.x + threadIdx.x; i < 2 * DD * DD;
         i += gridDim.x * blockDim.x) {
        int which = i >> 14;
        int j = i & 16383;
        float w = (which ? W2 : W1)[j];
        __nv_bfloat16 hi = __float2bfloat16(w);
        __nv_bfloat16 lo = __float2bfloat16(w - __bfloat162float(hi));
        g_Whi[which][j] = hi;
        g_Wlo[which][j] = lo;
    }
}

// ---------------- CSR aggregation (unchanged, near L2 floor) ---------------
__global__ void csr_agg_kernel(const float* __restrict__ X,
                               float* __restrict__ agg, int N) {
    int node = (int)((blockIdx.x * blockDim.x + threadIdx.x) >> 5);
    int lane = threadIdx.x & 31;
    if (node >= N) return;
    int j   = g_rowptr[node];
    int end = g_rowptr[node + 1];
    float4 a0 = make_float4(0.f, 0.f, 0.f, 0.f), a1 = a0, a2 = a0, a3 = a0;
    for (; j + 3 < end; j += 4) {
        int s0 = g_esrc[j], s1 = g_esrc[j + 1];
        int s2 = g_esrc[j + 2], s3 = g_esrc[j + 3];
        float4 v0 = *(const float4*)(X + (size_t)s0 * DD + lane * 4);
        float4 v1 = *(const float4*)(X + (size_t)s1 * DD + lane * 4);
        float4 v2 = *(const float4*)(X + (size_t)s2 * DD + lane * 4);
        float4 v3 = *(const float4*)(X + (size_t)s3 * DD + lane * 4);
        a0.x += v0.x; a0.y += v0.y; a0.z += v0.z; a0.w += v0.w;
        a1.x += v1.x; a1.y += v1.y; a1.z += v1.z; a1.w += v1.w;
        a2.x += v2.x; a2.y += v2.y; a2.z += v2.z; a2.w += v2.w;
        a3.x += v3.x; a3.y += v3.y; a3.z += v3.z; a3.w += v3.w;
    }
    for (; j < end; j++) {
        int s = g_esrc[j];
        float4 v = *(const float4*)(X + (size_t)s * DD + lane * 4);
        a0.x += v.x; a0.y += v.y; a0.z += v.z; a0.w += v.w;
    }
    a0.x += a1.x + a2.x + a3.x;
    a0.y += a1.y + a2.y + a3.y;
    a0.z += a1.z + a2.z + a3.z;
    a0.w += a1.w + a2.w + a3.w;
    *(float4*)(agg + (size_t)node * DD + lane * 4) = a0;
}

// ---------------- tensor-core GEMM + bias + ReLU (mma.sync bf16) -----------
// CTA: 128x128 tile, 256 threads = 8 warps (4 m-blocks x 2 n-blocks).
// Warp tile 32x64 = 2 m16-tiles x 8 n8-tiles.
// acc += Ahi*Whi + Alo*Whi + Ahi*Wlo  (fp32 accumulate; lo*lo dropped ~2^-18)
#define PITCH 136                       // bf16 elems; 272B rows, ldmatrix conflict-free
#define SM_AHI 0
#define SM_ALO (128 * PITCH)
#define SM_WHI (2 * 128 * PITCH)
#define SM_WLO (3 * 128 * PITCH)
#define GSM_TOTAL (4 * 128 * PITCH * (int)sizeof(__nv_bfloat16))

__global__ __launch_bounds__(256, 1)
void mma_gemm(const float* __restrict__ A, const __nv_bfloat16* __restrict__ Whi,
              const __nv_bfloat16* __restrict__ Wlo,
              const float* __restrict__ bias, float* __restrict__ out, int N) {
    extern __shared__ __nv_bfloat16 smem[];
    const uint32_t sb = smem_u32(smem);
    const int tid = threadIdx.x;
    const int lane = tid & 31;
    const int wid = tid >> 5;
    const int row0 = blockIdx.x * 128;

    // A tile: load fp32, split into bf16 hi/lo, store at pitch 136
    for (int i = tid; i < 128 * 32; i += 256) {
        int r = i >> 5;
        int kq = (i & 31) * 4;
        int gr = row0 + r;
        float4 v = (gr < N) ? *(const float4*)(A + (size_t)gr * DD + kq)
                            : make_float4(0.f, 0.f, 0.f, 0.f);
        __nv_bfloat16 hx = __float2bfloat16(v.x), hy = __float2bfloat16(v.y);
        __nv_bfloat16 hz = __float2bfloat16(v.z), hw = __float2bfloat16(v.w);
        __nv_bfloat16 lx = __float2bfloat16(v.x - __bfloat162float(hx));
        __nv_bfloat16 ly = __float2bfloat16(v.y - __bfloat162float(hy));
        __nv_bfloat16 lz = __float2bfloat16(v.z - __bfloat162float(hz));
        __nv_bfloat16 lw = __float2bfloat16(v.w - __bfloat162float(hw));
        ushort2 h01 = make_ushort2(__bfloat16_as_ushort(hx), __bfloat16_as_ushort(hy));
        ushort2 h23 = make_ushort2(__bfloat16_as_ushort(hz), __bfloat16_as_ushort(hw));
        ushort2 l01 = make_ushort2(__bfloat16_as_ushort(lx), __bfloat16_as_ushort(ly));
        ushort2 l23 = make_ushort2(__bfloat16_as_ushort(lz), __bfloat16_as_ushort(lw));
        int off = r * PITCH + kq;
        *(ushort2*)(smem + SM_AHI + off)     = h01;
        *(ushort2*)(smem + SM_AHI + off + 2) = h23;
        *(ushort2*)(smem + SM_ALO + off)     = l01;
        *(ushort2*)(smem + SM_ALO + off + 2) = l23;
    }
    // W tiles: straight copy, 16B chunks (global pitch 128, smem pitch 136)
    for (int i = tid; i < 128 * 16; i += 256) {
        int r = i >> 4;
        int q = (i & 15) * 8;
        *(uint4*)(smem + SM_WHI + r * PITCH + q) = *(const uint4*)(Whi + r * DD + q);
        *(uint4*)(smem + SM_WLO + r * PITCH + q) = *(const uint4*)(Wlo + r * DD + q);
    }
    __syncthreads();

    const int wm0 = (wid & 3) * 32;   // warp m offset in tile
    const int wc0 = (wid >> 2) * 64;  // warp n offset

    float acc[2][8][4];
#pragma unroll
    for (int m = 0; m < 2; m++)
#pragma unroll
        for (int n = 0; n < 8; n++)
#pragma unroll
            for (int q = 0; q < 4; q++) acc[m][n][q] = 0.f;

    // ldmatrix lane addressing: row = base_row + lane%16, kcol += (lane/16)*8
    const int lrow = lane & 15;
    const int lkof = (lane >> 4) * 8;

#pragma unroll
    for (int kk = 0; kk < 8; kk++) {
        const int k0 = kk * 16 + lkof;
        uint32_t ah[2][4], al[2][4], bh[4][4], bl[4][4];
#pragma unroll
        for (int mt = 0; mt < 2; mt++) {
            uint32_t ra = sb + (uint32_t)(((wm0 + mt * 16 + lrow) * PITCH + k0) * 2);
            ldm_x4(ah[mt][0], ah[mt][1], ah[mt][2], ah[mt][3], ra + SM_AHI * 2);
            ldm_x4(al[mt][0], al[mt][1], al[mt][2], al[mt][3], ra + SM_ALO * 2);
        }
#pragma unroll
        for (int np = 0; np < 4; np++) {
            uint32_t rb = sb + (uint32_t)(((wc0 + np * 16 + lrow) * PITCH + k0) * 2);
            ldm_x4(bh[np][0], bh[np][1], bh[np][2], bh[np][3], rb + SM_WHI * 2);
            ldm_x4(bl[np][0], bl[np][1], bl[np][2], bl[np][3], rb + SM_WLO * 2);
        }
#pragma unroll
        for (int mt = 0; mt < 2; mt++)
#pragma unroll
            for (int np = 0; np < 4; np++) {
                // n-pair np covers n8-tiles 2np ({r0,r2}) and 2np+1 ({r1,r3})
                mma_bf16(acc[mt][2 * np],     ah[mt], bh[np][0], bh[np][2]);
                mma_bf16(acc[mt][2 * np + 1], ah[mt], bh[np][1], bh[np][3]);
                mma_bf16(acc[mt][2 * np],     al[mt], bh[np][0], bh[np][2]);
                mma_bf16(acc[mt][2 * np + 1], al[mt], bh[np][1], bh[np][3]);
                mma_bf16(acc[mt][2 * np],     ah[mt], bl[np][0], bl[np][2]);
                mma_bf16(acc[mt][2 * np + 1], ah[mt], bl[np][1], bl[np][3]);
            }
    }

    // Epilogue: c-frag mapping — rows lane/4 and lane/4+8, cols (lane%4)*2,+1
    const int erow = lane >> 2;
    const int ecol = (lane & 3) * 2;
    float bb[8][2];
#pragma unroll
    for (int nt = 0; nt < 8; nt++) {
        bb[nt][0] = bias[wc0 + nt * 8 + ecol];
        bb[nt][1] = bias[wc0 + nt * 8 + ecol + 1];
    }
#pragma unroll
    for (int mt = 0; mt < 2; mt++) {
#pragma unroll
        for (int half = 0; half < 2; half++) {
            int gr = row0 + wm0 + mt * 16 + erow + half * 8;
            if (gr < N) {
                float* op = out + (size_t)gr * DD + wc0;
#pragma unroll
                for (int nt = 0; nt < 8; nt++) {
                    float2 o;
                    o.x = fmaxf(acc[mt][nt][2 * half]     + bb[nt][0], 0.f);
                    o.y = fmaxf(acc[mt][nt][2 * half + 1] + bb[nt][1], 0.f);
                    *(float2*)(op + nt * 8 + ecol) = o;
                }
            }
        }
    }
}

// ---------------------------------------------------------------------------
extern "C" void kernel_launch(void* const* d_in, const int* in_sizes, int n_in,
                              void* d_out, int out_size) {
    const float* x  = (const float*)d_in[0];
    const void*  ei = d_in[1];
    const float* W1 = (const float*)d_in[2];
    const float* b1 = (const float*)d_in[3];
    const float* W2 = (const float*)d_in[4];
    const float* b2 = (const float*)d_in[5];
    float* out      = (float*)d_out;

    int N = in_sizes[0] / DD;
    int E = in_sizes[1] / 2;

    float *agg, *h;
    __nv_bfloat16 *wh1, *wl1, *wh2, *wl2;
    cudaGetSymbolAddress((void**)&agg, g_agg);
    cudaGetSymbolAddress((void**)&h, g_h);
    cudaGetSymbolAddress((void**)&wh1, g_Whi);
    cudaGetSymbolAddress((void**)&wl1, g_Wlo);
    wh2 = wh1 + DD * DD;
    wl2 = wl1 + DD * DD;

    cudaFuncSetAttribute(mma_gemm, cudaFuncAttributeMaxDynamicSharedMemorySize,
                         GSM_TOTAL);

    int n       = N + 1;
    int nb      = (n + SCAN_CHUNK - 1) / SCAN_CHUNK;
    int cgrid   = (E + 255) / 256;
    int agrid   = (N * 32 + 255) / 256;
    int ggrid   = (N + 127) / 128;
    int n_check = E < 8 ? E : 8;

    // Build CSR + packed weights (once; reused by both layers)
    detect_kernel<<<1, 1>>>(ei, n_check, N);
    zero_cnt_kernel<<<(n + 255) / 256, 256>>>(n);
    convert_hist_kernel<<<cgrid, 256>>>(ei, E, N);
    scan1_kernel<<<nb, SCAN_CHUNK>>>(n);
    scan2_kernel<<<1, 32>>>(nb);
    scan3_kernel<<<(n + 255) / 256, 256>>>(n, N);
    place_kernel<<<cgrid, 256>>>(E);
    bpack_kernel<<<64, 256>>>(W1, W2);

    // Layer 1
    csr_agg_kernel<<<agrid, 256>>>(x, agg, N);
    mma_gemm<<<ggrid, 256, GSM_TOTAL>>>(agg, wh1, wl1, b1, h, N);

    // Layer 2
    csr_agg_kernel<<<agrid, 256>>>(h, agg, N);
    mma_gemm<<<ggrid, 256, GSM_TOTAL>>>(agg, wh2, wl2, b2, out, N);
}

// round 10
// speedup vs baseline: 2.4446x; 1.2138x over previous
#include <cuda_runtime.h>
#include <cuda_bf16.h>
#include <cstdint>

#define DD 128
#define NODES_MAX 100000
#define EDGES_MAX 1600000
#define SCAN_N (NODES_MAX + 1)
#define SCAN_CHUNK 1024

// ---------------- device scratch (no runtime allocation) -------------------
__device__ float  g_agg[(size_t)NODES_MAX * DD];
__device__ float  g_h[(size_t)NODES_MAX * DD];
__device__ int2   g_edge[EDGES_MAX];
__device__ int    g_esrc[EDGES_MAX];
__device__ int    g_rowptr[SCAN_N];
__device__ int    g_pos[NODES_MAX];
__device__ int    g_bsum[128];
__device__ int    g_is64;
// bf16 hi/lo weights, row-major [o][k] (the exact B layout row.col mma wants)
__device__ __align__(16) __nv_bfloat16 g_Whi[2][DD * DD];
__device__ __align__(16) __nv_bfloat16 g_Wlo[2][DD * DD];

// ---------------- warp-mma helpers (sm_80+ PTX, valid on compute_100) ------
__device__ __forceinline__ uint32_t smem_u32(const void* p) {
    uint32_t a;
    asm("{ .reg .u64 t; cvta.to.shared.u64 t, %1; cvt.u32.u64 %0, t; }"
        : "=r"(a) : "l"(p));
    return a;
}
__device__ __forceinline__ void ldm_x4(uint32_t& r0, uint32_t& r1,
                                       uint32_t& r2, uint32_t& r3,
                                       uint32_t addr) {
    asm volatile("ldmatrix.sync.aligned.m8n8.x4.shared.b16 {%0,%1,%2,%3}, [%4];"
                 : "=r"(r0), "=r"(r1), "=r"(r2), "=r"(r3) : "r"(addr));
}
__device__ __forceinline__ void mma_bf16(float* c, const uint32_t* a,
                                         uint32_t b0, uint32_t b1) {
    asm volatile(
        "mma.sync.aligned.m16n8k16.row.col.f32.bf16.bf16.f32 "
        "{%0,%1,%2,%3}, {%4,%5,%6,%7}, {%8,%9}, {%0,%1,%2,%3};"
        : "+f"(c[0]), "+f"(c[1]), "+f"(c[2]), "+f"(c[3])
        : "r"(a[0]), "r"(a[1]), "r"(a[2]), "r"(a[3]), "r"(b0), "r"(b1));
}

// ---------------- CSR build pipeline (unchanged) ---------------------------
__global__ void detect_kernel(const void* ei, int n_check, int n_nodes) {
    const long long* p = (const long long*)ei;
    int ok = 1;
    for (int i = 0; i < n_check; i++) {
        long long v = p[i];
        if (v < 0 || v >= n_nodes) { ok = 0; break; }
    }
    g_is64 = ok;
}

__global__ void zero_cnt_kernel(int n) {
    int i = blockIdx.x * blockDim.x + threadIdx.x;
    if (i < n) g_rowptr[i] = 0;
}

__global__ void convert_hist_kernel(const void* ei, int E, int N) {
    int e = blockIdx.x * blockDim.x + threadIdx.x;
    if (e >= E) return;
    int s, d;
    if (g_is64) {
        const long long* p = (const long long*)ei;
        s = (int)p[e];
        d = (int)p[(size_t)E + e];
    } else {
        const int* p = (const int*)ei;
        s = p[e];
        d = p[E + e];
    }
    if ((unsigned)s >= (unsigned)N) s = 0;
    if ((unsigned)d >= (unsigned)N) d = 0;
    g_edge[e] = make_int2(s, d);
    atomicAdd(&g_rowptr[d + 1], 1);
}

__global__ void scan1_kernel(int n) {
    __shared__ int sh[SCAN_CHUNK];
    int i = blockIdx.x * SCAN_CHUNK + threadIdx.x;
    sh[threadIdx.x] = (i < n) ? g_rowptr[i] : 0;
    __syncthreads();
    for (int off = 1; off < SCAN_CHUNK; off <<= 1) {
        int t = (threadIdx.x >= off) ? sh[threadIdx.x - off] : 0;
        __syncthreads();
        sh[threadIdx.x] += t;
        __syncthreads();
    }
    if (i < n) g_rowptr[i] = sh[threadIdx.x];
    if (threadIdx.x == SCAN_CHUNK - 1) g_bsum[blockIdx.x] = sh[threadIdx.x];
}

__global__ void scan2_kernel(int nb) {
    int lane = threadIdx.x;
    int carry = 0;
    for (int base = 0; base < nb; base += 32) {
        int i = base + lane;
        int orig = (i < nb) ? g_bsum[i] : 0;
        int v = orig;
#pragma unroll
        for (int off = 1; off < 32; off <<= 1) {
            int t = __shfl_up_sync(0xffffffffu, v, off);
            if (lane >= off) v += t;
        }
        if (i < nb) g_bsum[i] = carry + v - orig;
        carry += __shfl_sync(0xffffffffu, v, 31);
    }
}

__global__ void scan3_kernel(int n, int N) {
    int i = blockIdx.x * blockDim.x + threadIdx.x;
    if (i >= n) return;
    int v = g_rowptr[i] + g_bsum[i >> 10];
    g_rowptr[i] = v;
    if (i < N) g_pos[i] = v;
}

__global__ void place_kernel(int E) {
    int e = blockIdx.x * blockDim.x + threadIdx.x;
    if (e >= E) return;
    int2 ed = g_edge[e];
    int p = atomicAdd(&g_pos[ed.y], 1);
    g_esrc[p] = ed.x;
}

// Split weights into bf16 hi/lo (row-major [o][k]).
__global__ void bpack_kernel(const float* __restrict__ W1,
                             const float* __restrict__ W2) {
    for (int i = blockIdx.x * blockDim.x + threadIdx.x; i < 2 * DD * DD;
         i += gridDim.x * blockDim.x) {
        int which = i >> 14;
        int j = i & 16383;
        float w = (which ? W2 : W1)[j];
        __nv_bfloat16 hi = __float2bfloat16(w);
        __nv_bfloat16 lo = __float2bfloat16(w - __bfloat162float(hi));
        g_Whi[which][j] = hi;
        g_Wlo[which][j] = lo;
    }
}

// ---------------- CSR aggregation (unchanged, near L2 floor) ---------------
__global__ void csr_agg_kernel(const float* __restrict__ X,
                               float* __restrict__ agg, int N) {
    int node = (int)((blockIdx.x * blockDim.x + threadIdx.x) >> 5);
    int lane = threadIdx.x & 31;
    if (node >= N) return;
    int j   = g_rowptr[node];
    int end = g_rowptr[node + 1];
    float4 a0 = make_float4(0.f, 0.f, 0.f, 0.f), a1 = a0, a2 = a0, a3 = a0;
    for (; j + 3 < end; j += 4) {
        int s0 = g_esrc[j], s1 = g_esrc[j + 1];
        int s2 = g_esrc[j + 2], s3 = g_esrc[j + 3];
        float4 v0 = *(const float4*)(X + (size_t)s0 * DD + lane * 4);
        float4 v1 = *(const float4*)(X + (size_t)s1 * DD + lane * 4);
        float4 v2 = *(const float4*)(X + (size_t)s2 * DD + lane * 4);
        float4 v3 = *(const float4*)(X + (size_t)s3 * DD + lane * 4);
        a0.x += v0.x; a0.y += v0.y; a0.z += v0.z; a0.w += v0.w;
        a1.x += v1.x; a1.y += v1.y; a1.z += v1.z; a1.w += v1.w;
        a2.x += v2.x; a2.y += v2.y; a2.z += v2.z; a2.w += v2.w;
        a3.x += v3.x; a3.y += v3.y; a3.z += v3.z; a3.w += v3.w;
    }
    for (; j < end; j++) {
        int s = g_esrc[j];
        float4 v = *(const float4*)(X + (size_t)s * DD + lane * 4);
        a0.x += v.x; a0.y += v.y; a0.z += v.z; a0.w += v.w;
    }
    a0.x += a1.x + a2.x + a3.x;
    a0.y += a1.y + a2.y + a3.y;
    a0.z += a1.z + a2.z + a3.z;
    a0.w += a1.w + a2.w + a3.w;
    *(float4*)(agg + (size_t)node * DD + lane * 4) = a0;
}

// ---------------- tensor-core GEMM + bias + ReLU (mma.sync bf16) -----------
// CTA: 64x128 tile, 256 threads = 8 warps (2 m-blocks x 4 n-blocks).
// Warp tile 32x32 = 2 m16-tiles x 4 n8-tiles. Smem 102KB -> 2 CTAs/SM:
// one CTA's load/convert phase overlaps the other's mma phase.
// acc += Ahi*Whi + Alo*Whi + Ahi*Wlo  (fp32 accumulate; lo*lo dropped ~2^-18)
#define PITCH 136                       // bf16 elems; 272B rows, ldmatrix conflict-free
#define TILE_M 64
#define SM_AHI 0
#define SM_ALO (TILE_M * PITCH)
#define SM_WHI (2 * TILE_M * PITCH)
#define SM_WLO (2 * TILE_M * PITCH + 128 * PITCH)
#define GSM_TOTAL ((2 * TILE_M + 2 * 128) * PITCH * (int)sizeof(__nv_bfloat16))

__global__ __launch_bounds__(256, 2)
void mma_gemm(const float* __restrict__ A, const __nv_bfloat16* __restrict__ Whi,
              const __nv_bfloat16* __restrict__ Wlo,
              const float* __restrict__ bias, float* __restrict__ out, int N) {
    extern __shared__ __nv_bfloat16 smem[];
    const uint32_t sb = smem_u32(smem);
    const int tid = threadIdx.x;
    const int lane = tid & 31;
    const int wid = tid >> 5;
    const int row0 = blockIdx.x * TILE_M;

    // A tile (64 rows): load fp32, split into bf16 hi/lo, store at pitch 136
    for (int i = tid; i < TILE_M * 32; i += 256) {
        int r = i >> 5;
        int kq = (i & 31) * 4;
        int gr = row0 + r;
        float4 v = (gr < N) ? *(const float4*)(A + (size_t)gr * DD + kq)
                            : make_float4(0.f, 0.f, 0.f, 0.f);
        __nv_bfloat16 hx = __float2bfloat16(v.x), hy = __float2bfloat16(v.y);
        __nv_bfloat16 hz = __float2bfloat16(v.z), hw = __float2bfloat16(v.w);
        __nv_bfloat16 lx = __float2bfloat16(v.x - __bfloat162float(hx));
        __nv_bfloat16 ly = __float2bfloat16(v.y - __bfloat162float(hy));
        __nv_bfloat16 lz = __float2bfloat16(v.z - __bfloat162float(hz));
        __nv_bfloat16 lw = __float2bfloat16(v.w - __bfloat162float(hw));
        ushort2 h01 = make_ushort2(__bfloat16_as_ushort(hx), __bfloat16_as_ushort(hy));
        ushort2 h23 = make_ushort2(__bfloat16_as_ushort(hz), __bfloat16_as_ushort(hw));
        ushort2 l01 = make_ushort2(__bfloat16_as_ushort(lx), __bfloat16_as_ushort(ly));
        ushort2 l23 = make_ushort2(__bfloat16_as_ushort(lz), __bfloat16_as_ushort(lw));
        int off = r * PITCH + kq;
        *(ushort2*)(smem + SM_AHI + off)     = h01;
        *(ushort2*)(smem + SM_AHI + off + 2) = h23;
        *(ushort2*)(smem + SM_ALO + off)     = l01;
        *(ushort2*)(smem + SM_ALO + off + 2) = l23;
    }
    // W tiles (full 128x128): straight copy, 16B chunks
    for (int i = tid; i < 128 * 16; i += 256) {
        int r = i >> 4;
        int q = (i & 15) * 8;
        *(uint4*)(smem + SM_WHI + r * PITCH + q) = *(const uint4*)(Whi + r * DD + q);
        *(uint4*)(smem + SM_WLO + r * PITCH + q) = *(const uint4*)(Wlo + r * DD + q);
    }
    __syncthreads();

    const int wm0 = (wid & 1) * 32;   // warp m offset (2 blocks)
    const int wc0 = (wid >> 1) * 32;  // warp n offset (4 blocks)

    float acc[2][4][4];
#pragma unroll
    for (int m = 0; m < 2; m++)
#pragma unroll
        for (int n = 0; n < 4; n++)
#pragma unroll
            for (int q = 0; q < 4; q++) acc[m][n][q] = 0.f;

    const int lrow = lane & 15;
    const int lkof = (lane >> 4) * 8;

#pragma unroll
    for (int kk = 0; kk < 8; kk++) {
        const int k0 = kk * 16 + lkof;
        uint32_t ah[2][4], al[2][4], bh[2][4], bl[2][4];
#pragma unroll
        for (int mt = 0; mt < 2; mt++) {
            uint32_t ra = sb + (uint32_t)(((wm0 + mt * 16 + lrow) * PITCH + k0) * 2);
            ldm_x4(ah[mt][0], ah[mt][1], ah[mt][2], ah[mt][3], ra + SM_AHI * 2);
            ldm_x4(al[mt][0], al[mt][1], al[mt][2], al[mt][3], ra + SM_ALO * 2);
        }
#pragma unroll
        for (int np = 0; np < 2; np++) {
            uint32_t rb = sb + (uint32_t)(((wc0 + np * 16 + lrow) * PITCH + k0) * 2);
            ldm_x4(bh[np][0], bh[np][1], bh[np][2], bh[np][3], rb + SM_WHI * 2);
            ldm_x4(bl[np][0], bl[np][1], bl[np][2], bl[np][3], rb + SM_WLO * 2);
        }
#pragma unroll
        for (int mt = 0; mt < 2; mt++)
#pragma unroll
            for (int np = 0; np < 2; np++) {
                mma_bf16(acc[mt][2 * np],     ah[mt], bh[np][0], bh[np][2]);
                mma_bf16(acc[mt][2 * np + 1], ah[mt], bh[np][1], bh[np][3]);
                mma_bf16(acc[mt][2 * np],     al[mt], bh[np][0], bh[np][2]);
                mma_bf16(acc[mt][2 * np + 1], al[mt], bh[np][1], bh[np][3]);
                mma_bf16(acc[mt][2 * np],     ah[mt], bl[np][0], bl[np][2]);
                mma_bf16(acc[mt][2 * np + 1], ah[mt], bl[np][1], bl[np][3]);
            }
    }

    // Epilogue: c-frag rows lane/4 (+8), cols (lane%4)*2 (+1)
    const int erow = lane >> 2;
    const int ecol = (lane & 3) * 2;
    float bb[4][2];
#pragma unroll
    for (int nt = 0; nt < 4; nt++) {
        bb[nt][0] = bias[wc0 + nt * 8 + ecol];
        bb[nt][1] = bias[wc0 + nt * 8 + ecol + 1];
    }
#pragma unroll
    for (int mt = 0; mt < 2; mt++) {
#pragma unroll
        for (int half = 0; half < 2; half++) {
            int gr = row0 + wm0 + mt * 16 + erow + half * 8;
            if (gr < N) {
                float* op = out + (size_t)gr * DD + wc0;
#pragma unroll
                for (int nt = 0; nt < 4; nt++) {
                    float2 o;
                    o.x = fmaxf(acc[mt][nt][2 * half]     + bb[nt][0], 0.f);
                    o.y = fmaxf(acc[mt][nt][2 * half + 1] + bb[nt][1], 0.f);
                    *(float2*)(op + nt * 8 + ecol) = o;
                }
            }
        }
    }
}

// ---------------------------------------------------------------------------
extern "C" void kernel_launch(void* const* d_in, const int* in_sizes, int n_in,
                              void* d_out, int out_size) {
    const float* x  = (const float*)d_in[0];
    const void*  ei = d_in[1];
    const float* W1 = (const float*)d_in[2];
    const float* b1 = (const float*)d_in[3];
    const float* W2 = (const float*)d_in[4];
    const float* b2 = (const float*)d_in[5];
    float* out      = (float*)d_out;

    int N = in_sizes[0] / DD;
    int E = in_sizes[1] / 2;

    float *agg, *h;
    __nv_bfloat16 *wh1, *wl1, *wh2, *wl2;
    cudaGetSymbolAddress((void**)&agg, g_agg);
    cudaGetSymbolAddress((void**)&h, g_h);
    cudaGetSymbolAddress((void**)&wh1, g_Whi);
    cudaGetSymbolAddress((void**)&wl1, g_Wlo);
    wh2 = wh1 + DD * DD;
    wl2 = wl1 + DD * DD;

    cudaFuncSetAttribute(mma_gemm, cudaFuncAttributeMaxDynamicSharedMemorySize,
                         GSM_TOTAL);

    int n       = N + 1;
    int nb      = (n + SCAN_CHUNK - 1) / SCAN_CHUNK;
    int cgrid   = (E + 255) / 256;
    int agrid   = (N * 32 + 255) / 256;
    int ggrid   = (N + TILE_M - 1) / TILE_M;
    int n_check = E < 8 ? E : 8;

    // Build CSR + packed weights (once; reused by both layers)
    detect_kernel<<<1, 1>>>(ei, n_check, N);
    zero_cnt_kernel<<<(n + 255) / 256, 256>>>(n);
    convert_hist_kernel<<<cgrid, 256>>>(ei, E, N);
    scan1_kernel<<<nb, SCAN_CHUNK>>>(n);
    scan2_kernel<<<1, 32>>>(nb);
    scan3_kernel<<<(n + 255) / 256, 256>>>(n, N);
    place_kernel<<<cgrid, 256>>>(E);
    bpack_kernel<<<64, 256>>>(W1, W2);

    // Layer 1
    csr_agg_kernel<<<agrid, 256>>>(x, agg, N);
    mma_gemm<<<ggrid, 256, GSM_TOTAL>>>(agg, wh1, wl1, b1, h, N);

    // Layer 2
    csr_agg_kernel<<<agrid, 256>>>(h, agg, N);
    mma_gemm<<<ggrid, 256, GSM_TOTAL>>>(agg, wh2, wl2, b2, out, N);
}